// round 11
// baseline (speedup 1.0000x reference)
#include <cuda_runtime.h>
#include <math.h>
#include <stdint.h>

#define HIDDEN 4096
#define NEXP   128
#define TOPK   8
#define TM     128
#define KCH    32

#define KT_CHUNKS 50                  // tensor path: k in [0, 1600)
#define KF_CHUNKS 78                  // fma path:    k in [1600, 4096)
#define K_T       1600

// tensor-path smem (PITCH-36 fp32 k8 regions, proven in R10)
#define PITCH   36
#define K8S     (128 * PITCH + 32)    // 4640
#define TEN_BOFF (4 * K8S)            // B region offset inside a stage (18560)
#define TEN_STAGE (8 * K8S)           // 37120
#define TEN0    0
#define TEN1    TEN_STAGE

// fma-path smem (plain k-major fp32, 132-float pitch)
#define FPITCH  528                   // bytes per k-row (132 floats)
#define FMA_A   0
#define FMA_B   (32 * FPITCH)         // 16896
#define FMA_STAGE (2 * 32 * FPITCH)   // 33792
#define FMA0    (2 * TEN_STAGE)       // 74240
#define FMA1    (FMA0 + FMA_STAGE)    // 108032

#define SMEM_BYTES (FMA1 + FMA_STAGE) // 141824
#define LPITCH  132

#define DELTA   1.5e-4f
#define RB      8

__device__ int g_ctr;
__device__ int g_list[16384];

#define BAR(id) asm volatile("bar.sync %0, %1;" :: "r"(id), "r"(128) : "memory")

// Split adjacent-k float pair into packed bf16x2 hi and exact-residual lo.
__device__ __forceinline__ void split_bf16(float x, float y, uint32_t& h, uint32_t& l) {
    asm("cvt.rn.bf16x2.f32 %0, %1, %2;" : "=r"(h) : "f"(y), "f"(x));
    float h0 = __uint_as_float(h << 16);
    float h1 = __uint_as_float(h & 0xffff0000u);
    asm("cvt.rn.bf16x2.f32 %0, %1, %2;" : "=r"(l) : "f"(y - h1), "f"(x - h0));
}

__device__ __forceinline__ void mma16(float d[4], const uint32_t a[4], const uint32_t b[2]) {
    asm volatile(
        "mma.sync.aligned.m16n8k16.row.col.f32.bf16.bf16.f32 "
        "{%0,%1,%2,%3}, {%4,%5,%6,%7}, {%8,%9}, {%0,%1,%2,%3};\n"
        : "+f"(d[0]), "+f"(d[1]), "+f"(d[2]), "+f"(d[3])
        : "r"(a[0]), "r"(a[1]), "r"(a[2]), "r"(a[3]),
          "r"(b[0]), "r"(b[1]));
}

__device__ __forceinline__ void ffma2(unsigned long long& d,
                                      unsigned long long a,
                                      unsigned long long b) {
    asm("fma.rn.f32x2 %0, %1, %2, %0;" : "+l"(d) : "l"(a), "l"(b));
}
__device__ __forceinline__ unsigned long long dup2(float v) {
    unsigned long long r;
    asm("mov.b64 %0, {%1, %1};" : "=l"(r) : "f"(v));
    return r;
}

__global__ void zero_ctr_kernel() { g_ctr = 0; }

// ---------------------------------------------------------------------------
// Hybrid dual-pipe router. Warps 0-3: bf16x3 mma path over k[0,1600).
// Warps 4-7: FFMA2 fp32 path over k[1600,4096). Partial logits merged in
// smem, then top-9 risk detection; risky tokens refined exactly in fp32.
// ---------------------------------------------------------------------------
__global__ void __launch_bounds__(256, 1) router_fused(
    const float* __restrict__ X, const float* __restrict__ W,
    const float* __restrict__ bias, float* __restrict__ out, int T)
{
    extern __shared__ char smem[];
    const int tid  = threadIdx.x;
    const int wid  = tid >> 5;
    const int lane = tid & 31;
    const int m0   = blockIdx.x * TM;

    // tensor accumulators (warps 0-3) : 4 m-tiles x 8 n-tiles
    float acc[4][8][4];
    // fma accumulators (warps 4-7)    : 16 tokens x 4 expert-pairs
    unsigned long long acc2[16][4];

    if (wid < 4) {
        // ================= TENSOR PATH (warps 0-3, tid 0..127) ==============
        const int wm = (wid >> 1) & 1;
        const int wn = wid & 1;
        const int g  = lane >> 2;
        const int t  = lane & 3;
        const int c4  = tid & 7;
        const int k8p = c4 >> 1;
        const int kkb = (c4 & 1) * 4;

#pragma unroll
        for (int i = 0; i < 4; i++)
#pragma unroll
            for (int j = 0; j < 8; j++)
#pragma unroll
                for (int q = 0; q < 4; q++) acc[i][j][q] = 0.f;

        // prologue: produce chunk 0 fully into stage TEN0
#pragma unroll
        for (int i = 0; i < 8; i++) {
            const int row = (tid >> 3) + 16 * i;
            float4 va = *(const float4*)(X + (size_t)(m0 + row) * HIDDEN + c4 * 4);
            float4 vb = *(const float4*)(W + (size_t)row * HIDDEN + c4 * 4);
            float* pA = (float*)(smem + TEN0 + k8p * K8S + row * PITCH + kkb * 4);
            pA[0] = va.x; pA[1] = va.y; pA[2] = va.z; pA[3] = va.w;
            float* pB = (float*)(smem + TEN0 + TEN_BOFF + k8p * K8S + row * PITCH + kkb * 4);
            pB[0] = vb.x; pB[1] = vb.y; pB[2] = vb.z; pB[3] = vb.w;
        }

        float4 xa[4], wa[4];
        for (int c = 0; c < KT_CHUNKS; c++) {
            BAR(1);
            const char* sp = smem + ((c & 1) ? TEN1 : TEN0);

            if (c + 1 < KT_CHUNKS) {
                const int k0 = (c + 1) * KCH;
#pragma unroll
                for (int i = 0; i < 4; i++) {
                    const int row = (tid >> 3) + 16 * i;
                    xa[i] = *(const float4*)(X + (size_t)(m0 + row) * HIDDEN + k0 + c4 * 4);
                    wa[i] = *(const float4*)(W + (size_t)row * HIDDEN + k0 + c4 * 4);
                }
            }

#pragma unroll
            for (int h = 0; h < 2; h++) {
                const char* a0p = sp + (2 * h + 0) * K8S;
                const char* a1p = sp + (2 * h + 1) * K8S;
                const char* b0p = sp + TEN_BOFF + (2 * h + 0) * K8S;
                const char* b1p = sp + TEN_BOFF + (2 * h + 1) * K8S;
#pragma unroll
                for (int jh = 0; jh < 2; jh++) {
                    uint32_t bh[4][2], bl[4][2];
#pragma unroll
                    for (int jj = 0; jj < 4; jj++) {
                        const int e = wn * 64 + (jh * 4 + jj) * 8 + g;
                        const char* r0 = b0p + e * PITCH + t * 8;
                        const char* r1 = b1p + e * PITCH + t * 8;
                        split_bf16(*(const float*)(r0), *(const float*)(r0 + 4),
                                   bh[jj][0], bl[jj][0]);
                        split_bf16(*(const float*)(r1), *(const float*)(r1 + 4),
                                   bh[jj][1], bl[jj][1]);
                    }
#pragma unroll
                    for (int i = 0; i < 4; i++) {
                        const int ra = wm * 64 + i * 16 + g;
                        const char* q0 = a0p + ra * PITCH + t * 8;
                        const char* q1 = a0p + (ra + 8) * PITCH + t * 8;
                        const char* q2 = a1p + ra * PITCH + t * 8;
                        const char* q3 = a1p + (ra + 8) * PITCH + t * 8;
                        uint32_t ah[4], al[4];
                        split_bf16(*(const float*)(q0), *(const float*)(q0 + 4), ah[0], al[0]);
                        split_bf16(*(const float*)(q1), *(const float*)(q1 + 4), ah[1], al[1]);
                        split_bf16(*(const float*)(q2), *(const float*)(q2 + 4), ah[2], al[2]);
                        split_bf16(*(const float*)(q3), *(const float*)(q3 + 4), ah[3], al[3]);
#pragma unroll
                        for (int jj = 0; jj < 4; jj++) {
                            const int j = jh * 4 + jj;
                            mma16(acc[i][j], ah, bh[jj]);
                            mma16(acc[i][j], al, bh[jj]);
                            mma16(acc[i][j], ah, bl[jj]);
                        }
                    }
                }
            }

            if (c + 1 < KT_CHUNKS) {
                char* sn = (char*)smem + (((c + 1) & 1) ? TEN1 : TEN0);
                const int k0 = (c + 1) * KCH;
#pragma unroll
                for (int i = 0; i < 4; i++) {
                    const int row = (tid >> 3) + 16 * i;
                    float* pA = (float*)(sn + k8p * K8S + row * PITCH + kkb * 4);
                    pA[0] = xa[i].x; pA[1] = xa[i].y; pA[2] = xa[i].z; pA[3] = xa[i].w;
                    float* pB = (float*)(sn + TEN_BOFF + k8p * K8S + row * PITCH + kkb * 4);
                    pB[0] = wa[i].x; pB[1] = wa[i].y; pB[2] = wa[i].z; pB[3] = wa[i].w;
                }
#pragma unroll
                for (int i = 4; i < 8; i++) {
                    const int row = (tid >> 3) + 16 * i;
                    float4 va = *(const float4*)(X + (size_t)(m0 + row) * HIDDEN + k0 + c4 * 4);
                    float4 vb = *(const float4*)(W + (size_t)row * HIDDEN + k0 + c4 * 4);
                    float* pA = (float*)(sn + k8p * K8S + row * PITCH + kkb * 4);
                    pA[0] = va.x; pA[1] = va.y; pA[2] = va.z; pA[3] = va.w;
                    float* pB = (float*)(sn + TEN_BOFF + k8p * K8S + row * PITCH + kkb * 4);
                    pB[0] = vb.x; pB[1] = vb.y; pB[2] = vb.z; pB[3] = vb.w;
                }
            }
        }
    } else {
        // ================= FMA PATH (warps 4-7, tidf 0..127) ================
        const int tidf = tid - 128;
        const int w4 = wid - 4;
        const int fm = (w4 >> 1) & 1;
        const int fn = w4 & 1;
        const int lt = lane >> 3;          // token group (0..3)
        const int le = lane & 7;           // expert group (0..7)
        const int c4 = tidf & 7;

#pragma unroll
        for (int i = 0; i < 16; i++)
#pragma unroll
            for (int j = 0; j < 4; j++) acc2[i][j] = 0ull;

        // prologue: produce chunk 0 (k0 = K_T) into FMA0
#pragma unroll
        for (int i = 0; i < 8; i++) {
            const int row = (tidf >> 3) + 16 * i;
            float4 va = *(const float4*)(X + (size_t)(m0 + row) * HIDDEN + K_T + c4 * 4);
            float4 vb = *(const float4*)(W + (size_t)row * HIDDEN + K_T + c4 * 4);
            const float av[4] = {va.x, va.y, va.z, va.w};
            const float bv[4] = {vb.x, vb.y, vb.z, vb.w};
#pragma unroll
            for (int j = 0; j < 4; j++) {
                *(float*)(smem + FMA0 + FMA_A + (c4 * 4 + j) * FPITCH + row * 4) = av[j];
                *(float*)(smem + FMA0 + FMA_B + (c4 * 4 + j) * FPITCH + row * 4) = bv[j];
            }
        }

        const int tokb = fm * 64 + lt * 16;      // this thread's first token
        const int expb = fn * 64 + le * 8;       // this thread's first expert

        float4 xa[4], wa[4];
        for (int c = 0; c < KF_CHUNKS; c++) {
            BAR(2);
            const char* sp = smem + ((c & 1) ? FMA1 : FMA0);

            if (c + 1 < KF_CHUNKS) {
                const int k0 = K_T + (c + 1) * KCH;
#pragma unroll
                for (int i = 0; i < 4; i++) {
                    const int row = (tidf >> 3) + 16 * i;
                    xa[i] = *(const float4*)(X + (size_t)(m0 + row) * HIDDEN + k0 + c4 * 4);
                    wa[i] = *(const float4*)(W + (size_t)row * HIDDEN + k0 + c4 * 4);
                }
            }

#pragma unroll 4
            for (int kr = 0; kr < KCH; kr++) {
                const char* ab = sp + FMA_A + kr * FPITCH + tokb * 4;
                float4 f0 = *(const float4*)(ab);
                float4 f1 = *(const float4*)(ab + 16);
                float4 f2 = *(const float4*)(ab + 32);
                float4 f3 = *(const float4*)(ab + 48);
                unsigned long long ad[16];
                ad[0]  = dup2(f0.x); ad[1]  = dup2(f0.y); ad[2]  = dup2(f0.z); ad[3]  = dup2(f0.w);
                ad[4]  = dup2(f1.x); ad[5]  = dup2(f1.y); ad[6]  = dup2(f1.z); ad[7]  = dup2(f1.w);
                ad[8]  = dup2(f2.x); ad[9]  = dup2(f2.y); ad[10] = dup2(f2.z); ad[11] = dup2(f2.w);
                ad[12] = dup2(f3.x); ad[13] = dup2(f3.y); ad[14] = dup2(f3.z); ad[15] = dup2(f3.w);

                const char* bb = sp + FMA_B + kr * FPITCH + expb * 4;
                unsigned long long b[4];
                b[0] = *(const unsigned long long*)(bb);
                b[1] = *(const unsigned long long*)(bb + 8);
                b[2] = *(const unsigned long long*)(bb + 16);
                b[3] = *(const unsigned long long*)(bb + 24);
#pragma unroll
                for (int i = 0; i < 16; i++)
#pragma unroll
                    for (int j = 0; j < 4; j++)
                        ffma2(acc2[i][j], ad[i], b[j]);
            }

            if (c + 1 < KF_CHUNKS) {
                char* sn = (char*)smem + (((c + 1) & 1) ? FMA1 : FMA0);
                const int k0 = K_T + (c + 1) * KCH;
#pragma unroll
                for (int i = 0; i < 4; i++) {
                    const int row = (tidf >> 3) + 16 * i;
                    const float av[4] = {xa[i].x, xa[i].y, xa[i].z, xa[i].w};
                    const float bv[4] = {wa[i].x, wa[i].y, wa[i].z, wa[i].w};
#pragma unroll
                    for (int j = 0; j < 4; j++) {
                        *(float*)(sn + FMA_A + (c4 * 4 + j) * FPITCH + row * 4) = av[j];
                        *(float*)(sn + FMA_B + (c4 * 4 + j) * FPITCH + row * 4) = bv[j];
                    }
                }
#pragma unroll
                for (int i = 4; i < 8; i++) {
                    const int row = (tidf >> 3) + 16 * i;
                    float4 va = *(const float4*)(X + (size_t)(m0 + row) * HIDDEN + k0 + c4 * 4);
                    float4 vb = *(const float4*)(W + (size_t)row * HIDDEN + k0 + c4 * 4);
                    const float av[4] = {va.x, va.y, va.z, va.w};
                    const float bv[4] = {vb.x, vb.y, vb.z, vb.w};
#pragma unroll
                    for (int j = 0; j < 4; j++) {
                        *(float*)(sn + FMA_A + (c4 * 4 + j) * FPITCH + row * 4) = av[j];
                        *(float*)(sn + FMA_B + (c4 * 4 + j) * FPITCH + row * 4) = bv[j];
                    }
                }
            }
        }
    }

    // ================= MERGE LOGITS =================
    __syncthreads();
    float* L = (float*)smem;   // [128][LPITCH]
    if (wid < 4) {
        const int wm = (wid >> 1) & 1;
        const int wn = wid & 1;
        const int g  = lane >> 2;
        const int t  = lane & 3;
#pragma unroll
        for (int i = 0; i < 4; i++) {
            const int r0 = wm * 64 + i * 16 + g;
#pragma unroll
            for (int j = 0; j < 8; j++) {
                const int c0 = wn * 64 + j * 8 + t * 2;
                *(float2*)&L[r0 * LPITCH + c0]       = make_float2(acc[i][j][0], acc[i][j][1]);
                *(float2*)&L[(r0 + 8) * LPITCH + c0] = make_float2(acc[i][j][2], acc[i][j][3]);
            }
        }
    }
    __syncthreads();
    if (wid >= 4) {
        const int w4 = wid - 4;
        const int fm = (w4 >> 1) & 1;
        const int fn = w4 & 1;
        const int lt = lane >> 3;
        const int le = lane & 7;
#pragma unroll
        for (int i = 0; i < 16; i++) {
            const int tok = fm * 64 + lt * 16 + i;
#pragma unroll
            for (int j = 0; j < 4; j++) {
                const int e = fn * 64 + le * 8 + j * 2;
                float2 v = *(float2*)&acc2[i][j];
                L[tok * LPITCH + e]     += v.x;
                L[tok * LPITCH + e + 1] += v.y;
            }
        }
    }
    __syncthreads();

    // ---- top-9 with risk detection; warp w handles rows w*16..w*16+15 ----
    float bv[4];
#pragma unroll
    for (int q = 0; q < 4; q++) bv[q] = bias[q * 32 + lane];

    for (int rr = 0; rr < 16; rr++) {
        const int row = wid * 16 + rr;
        const float* Lr = L + row * LPITCH;

        float sv[4], wv[4];
#pragma unroll
        for (int q = 0; q < 4; q++) {
            float sc = 1.f / (1.f + expf(-Lr[q * 32 + lane]));
            wv[q] = sc;
            sv[q] = sc + bv[q];
        }

        float wsel[TOPK];
        int   isel[TOPK];
        float wsum = 0.f;
        float prev = 0.f, mingap = INFINITY;

#pragma unroll
        for (int k = 0; k < TOPK + 1; k++) {
            float bs = -INFINITY; int bi = 0x7fffffff; float bw = 0.f;
#pragma unroll
            for (int q = 0; q < 4; q++) {
                int e = q * 32 + lane;
                if (sv[q] > bs || (sv[q] == bs && e < bi)) { bs = sv[q]; bi = e; bw = wv[q]; }
            }
#pragma unroll
            for (int off = 16; off; off >>= 1) {
                float os = __shfl_xor_sync(0xffffffffu, bs, off);
                int   oi = __shfl_xor_sync(0xffffffffu, bi, off);
                float ow = __shfl_xor_sync(0xffffffffu, bw, off);
                if (os > bs || (os == bs && oi < bi)) { bs = os; bi = oi; bw = ow; }
            }
            if (k > 0) mingap = fminf(mingap, prev - bs);
            prev = bs;
            if (k < TOPK) {
                isel[k] = bi; wsel[k] = bw; wsum += bw;
#pragma unroll
                for (int q = 0; q < 4; q++)
                    if (q * 32 + lane == bi) sv[q] = -INFINITY;
            }
        }

        if (lane == 0) {
            const int token = m0 + row;
            float inv = 1.f / (wsum + 1e-20f);   // ROUTED_SCALING = 1.0
#pragma unroll
            for (int k = 0; k < TOPK; k++) {
                out[(size_t)token * TOPK + k]                    = (float)isel[k];
                out[(size_t)T * TOPK + (size_t)token * TOPK + k] = wsel[k] * inv;
            }
            if (!(mingap >= DELTA)) {
                int idx = atomicAdd(&g_ctr, 1);
                g_list[idx] = token;
            }
        }
    }
}

// ---------------------------------------------------------------------------
// Exact fp32 refine of risky tokens (proven, unchanged).
// ---------------------------------------------------------------------------
__global__ void __launch_bounds__(256) refine_kernel(
    const float* __restrict__ X, const float* __restrict__ W,
    const float* __restrict__ bias, float* __restrict__ out, int T)
{
    __shared__ float Xs[RB][512];
    __shared__ float S[RB][NEXP];
    __shared__ int   tks[RB];

    const int tid  = threadIdx.x;
    const int e    = tid & 127;
    const int tg   = tid >> 7;
    const int wid  = tid >> 5;
    const int lane = tid & 31;
    const int R    = g_ctr;

    for (int b = blockIdx.x; b * RB < R; b += gridDim.x) {
        if (tid < RB) {
            int i = b * RB + tid;
            tks[tid] = (i < R) ? g_list[i] : -1;
        }
        __syncthreads();

        float acc[4] = {0.f, 0.f, 0.f, 0.f};
        const float* wrow = W + (size_t)e * HIDDEN;

        for (int c = 0; c < 8; c++) {
            const int k0 = c * 512;
#pragma unroll
            for (int i = 0; i < 4; i++) {
                int s   = tid + 256 * i;
                int tok = s >> 7;
                int f4  = s & 127;
                int tt  = tks[tok] < 0 ? 0 : tks[tok];
                *(float4*)&Xs[tok][f4 * 4] =
                    *(const float4*)(X + (size_t)tt * HIDDEN + k0 + f4 * 4);
            }
            __syncthreads();
#pragma unroll 4
            for (int f4 = 0; f4 < 128; f4++) {
                float4 w4 = *(const float4*)(wrow + k0 + f4 * 4);
#pragma unroll
                for (int j = 0; j < 4; j++) {
                    const float* xr = &Xs[tg * 4 + j][f4 * 4];
                    acc[j] = fmaf(w4.x, xr[0],
                             fmaf(w4.y, xr[1],
                             fmaf(w4.z, xr[2],
                             fmaf(w4.w, xr[3], acc[j]))));
                }
            }
            __syncthreads();
        }
#pragma unroll
        for (int j = 0; j < 4; j++) S[tg * 4 + j][e] = acc[j];
        __syncthreads();

        if (wid < RB && tks[wid] >= 0) {
            const int token = tks[wid];
            float sv[4], wv[4];
#pragma unroll
            for (int q = 0; q < 4; q++) {
                int ee = q * 32 + lane;
                float sc = 1.f / (1.f + expf(-S[wid][ee]));
                wv[q] = sc;
                sv[q] = sc + bias[ee];
            }
            float wsel[TOPK]; int isel[TOPK]; float wsum = 0.f;
#pragma unroll
            for (int k = 0; k < TOPK; k++) {
                float bs = -INFINITY; int bi = 0x7fffffff; float bw = 0.f;
#pragma unroll
                for (int q = 0; q < 4; q++) {
                    int ee = q * 32 + lane;
                    if (sv[q] > bs || (sv[q] == bs && ee < bi)) { bs = sv[q]; bi = ee; bw = wv[q]; }
                }
#pragma unroll
                for (int off = 16; off; off >>= 1) {
                    float os = __shfl_xor_sync(0xffffffffu, bs, off);
                    int   oi = __shfl_xor_sync(0xffffffffu, bi, off);
                    float ow = __shfl_xor_sync(0xffffffffu, bw, off);
                    if (os > bs || (os == bs && oi < bi)) { bs = os; bi = oi; bw = ow; }
                }
                isel[k] = bi; wsel[k] = bw; wsum += bw;
#pragma unroll
                for (int q = 0; q < 4; q++)
                    if (q * 32 + lane == bi) sv[q] = -INFINITY;
            }
            if (lane == 0) {
                float inv = 1.f / (wsum + 1e-20f);
#pragma unroll
                for (int k = 0; k < TOPK; k++) {
                    out[(size_t)token * TOPK + k]                    = (float)isel[k];
                    out[(size_t)T * TOPK + (size_t)token * TOPK + k] = wsel[k] * inv;
                }
            }
        }
        __syncthreads();
    }
}

// ---------------------------------------------------------------------------
extern "C" void kernel_launch(void* const* d_in, const int* in_sizes, int n_in,
                              void* d_out, int out_size)
{
    const float* X    = (const float*)d_in[0];
    const float* W    = (const float*)d_in[1];
    const float* bias = (const float*)d_in[2];
    float* out = (float*)d_out;

    const int T = in_sizes[0] / HIDDEN;          // 16384

    cudaFuncSetAttribute(router_fused,
                         cudaFuncAttributeMaxDynamicSharedMemorySize, SMEM_BYTES);

    zero_ctr_kernel<<<1, 1>>>();
    router_fused<<<T / TM, 256, SMEM_BYTES>>>(X, W, bias, out, T);
    refine_kernel<<<256, 256>>>(X, W, bias, out, T);
}

// round 12
// speedup vs baseline: 1.1505x; 1.1505x over previous
#include <cuda_runtime.h>
#include <math.h>
#include <stdint.h>

#define HIDDEN 4096
#define NEXP   128
#define TOPK   8
#define TM     128
#define KCH    32

#define KT_CHUNKS 87                  // tensor path: k in [0, 2784)
#define KF_CHUNKS 41                  // fma path:    k in [2784, 4096)
#define K_T       2784

// tensor-path smem (PITCH-36 fp32 k8 regions, proven in R10)
#define PITCH   36
#define K8S     (128 * PITCH + 32)    // 4640
#define TEN_BOFF (4 * K8S)            // B region offset inside a stage (18560)
#define TEN_STAGE (8 * K8S)           // 37120
#define TEN0    0
#define TEN1    TEN_STAGE

// fma-path smem (plain k-major fp32, 132-float pitch)
#define FPITCH  528                   // bytes per k-row (132 floats)
#define FMA_A   0
#define FMA_B   (32 * FPITCH)         // 16896
#define FMA_STAGE (2 * 32 * FPITCH)   // 33792
#define FMA0    (2 * TEN_STAGE)       // 74240
#define FMA1    (FMA0 + FMA_STAGE)    // 108032

#define SMEM_BYTES (FMA1 + FMA_STAGE) // 141824
#define LPITCH  132                   // partial-logits pitch (floats)
// L  (tensor partial) at smem + 0       (67584 B over dead TEN stages)
// L2 (fma    partial) at smem + FMA0    (67584 B over dead FMA stages)

#define DELTA   1.5e-4f
#define RB      8

__device__ int g_ctr;
__device__ int g_list[16384];

#define BAR(id) asm volatile("bar.sync %0, %1;" :: "r"(id), "r"(128) : "memory")

__device__ __forceinline__ void split_bf16(float x, float y, uint32_t& h, uint32_t& l) {
    asm("cvt.rn.bf16x2.f32 %0, %1, %2;" : "=r"(h) : "f"(y), "f"(x));
    float h0 = __uint_as_float(h << 16);
    float h1 = __uint_as_float(h & 0xffff0000u);
    asm("cvt.rn.bf16x2.f32 %0, %1, %2;" : "=r"(l) : "f"(y - h1), "f"(x - h0));
}

__device__ __forceinline__ void mma16(float d[4], const uint32_t a[4], const uint32_t b[2]) {
    asm volatile(
        "mma.sync.aligned.m16n8k16.row.col.f32.bf16.bf16.f32 "
        "{%0,%1,%2,%3}, {%4,%5,%6,%7}, {%8,%9}, {%0,%1,%2,%3};\n"
        : "+f"(d[0]), "+f"(d[1]), "+f"(d[2]), "+f"(d[3])
        : "r"(a[0]), "r"(a[1]), "r"(a[2]), "r"(a[3]),
          "r"(b[0]), "r"(b[1]));
}

__device__ __forceinline__ void ffma2(unsigned long long& d,
                                      unsigned long long a,
                                      unsigned long long b) {
    asm("fma.rn.f32x2 %0, %1, %2, %0;" : "+l"(d) : "l"(a), "l"(b));
}
__device__ __forceinline__ unsigned long long dup2(float v) {
    unsigned long long r;
    asm("mov.b64 %0, {%1, %1};" : "=l"(r) : "f"(v));
    return r;
}

__global__ void zero_ctr_kernel() { g_ctr = 0; }

// ---------------------------------------------------------------------------
// Hybrid dual-pipe router. Warps 0-3: bf16x3 mma path over k[0,2784).
// Warps 4-7: FFMA2 fp32 path over k[2784,4096). Accumulators are
// branch-scoped (no cross-branch liveness -> no spills); each path dumps its
// partial logits into its OWN smem region, then top-9 reads the sum.
// ---------------------------------------------------------------------------
__global__ void __launch_bounds__(256, 1) router_fused(
    const float* __restrict__ X, const float* __restrict__ W,
    const float* __restrict__ bias, float* __restrict__ out, int T)
{
    extern __shared__ char smem[];
    const int tid  = threadIdx.x;
    const int wid  = tid >> 5;
    const int lane = tid & 31;
    const int m0   = blockIdx.x * TM;

    float* L  = (float*)smem;            // tensor partial [128][LPITCH]
    float* L2 = (float*)(smem + FMA0);   // fma partial    [128][LPITCH]

    if (wid < 4) {
        // ================= TENSOR PATH (warps 0-3, tid 0..127) ==============
        const int wm = (wid >> 1) & 1;
        const int wn = wid & 1;
        const int g  = lane >> 2;
        const int t  = lane & 3;
        const int c4  = tid & 7;
        const int k8p = c4 >> 1;
        const int kkb = (c4 & 1) * 4;

        float acc[4][8][4];
#pragma unroll
        for (int i = 0; i < 4; i++)
#pragma unroll
            for (int j = 0; j < 8; j++)
#pragma unroll
                for (int q = 0; q < 4; q++) acc[i][j][q] = 0.f;

        // prologue: produce chunk 0 fully into stage TEN0
#pragma unroll
        for (int i = 0; i < 8; i++) {
            const int row = (tid >> 3) + 16 * i;
            float4 va = *(const float4*)(X + (size_t)(m0 + row) * HIDDEN + c4 * 4);
            float4 vb = *(const float4*)(W + (size_t)row * HIDDEN + c4 * 4);
            float* pA = (float*)(smem + TEN0 + k8p * K8S + row * PITCH + kkb * 4);
            pA[0] = va.x; pA[1] = va.y; pA[2] = va.z; pA[3] = va.w;
            float* pB = (float*)(smem + TEN0 + TEN_BOFF + k8p * K8S + row * PITCH + kkb * 4);
            pB[0] = vb.x; pB[1] = vb.y; pB[2] = vb.z; pB[3] = vb.w;
        }

        float4 xa[4], wa[4];
        for (int c = 0; c < KT_CHUNKS; c++) {
            BAR(1);
            const char* sp = smem + ((c & 1) ? TEN1 : TEN0);

            if (c + 1 < KT_CHUNKS) {
                const int k0 = (c + 1) * KCH;
#pragma unroll
                for (int i = 0; i < 4; i++) {
                    const int row = (tid >> 3) + 16 * i;
                    xa[i] = *(const float4*)(X + (size_t)(m0 + row) * HIDDEN + k0 + c4 * 4);
                    wa[i] = *(const float4*)(W + (size_t)row * HIDDEN + k0 + c4 * 4);
                }
            }

#pragma unroll
            for (int h = 0; h < 2; h++) {
                const char* a0p = sp + (2 * h + 0) * K8S;
                const char* a1p = sp + (2 * h + 1) * K8S;
                const char* b0p = sp + TEN_BOFF + (2 * h + 0) * K8S;
                const char* b1p = sp + TEN_BOFF + (2 * h + 1) * K8S;
#pragma unroll
                for (int jh = 0; jh < 2; jh++) {
                    uint32_t bh[4][2], bl[4][2];
#pragma unroll
                    for (int jj = 0; jj < 4; jj++) {
                        const int e = wn * 64 + (jh * 4 + jj) * 8 + g;
                        const char* r0 = b0p + e * PITCH + t * 8;
                        const char* r1 = b1p + e * PITCH + t * 8;
                        split_bf16(*(const float*)(r0), *(const float*)(r0 + 4),
                                   bh[jj][0], bl[jj][0]);
                        split_bf16(*(const float*)(r1), *(const float*)(r1 + 4),
                                   bh[jj][1], bl[jj][1]);
                    }
#pragma unroll
                    for (int i = 0; i < 4; i++) {
                        const int ra = wm * 64 + i * 16 + g;
                        const char* q0 = a0p + ra * PITCH + t * 8;
                        const char* q1 = a0p + (ra + 8) * PITCH + t * 8;
                        const char* q2 = a1p + ra * PITCH + t * 8;
                        const char* q3 = a1p + (ra + 8) * PITCH + t * 8;
                        uint32_t ah[4], al[4];
                        split_bf16(*(const float*)(q0), *(const float*)(q0 + 4), ah[0], al[0]);
                        split_bf16(*(const float*)(q1), *(const float*)(q1 + 4), ah[1], al[1]);
                        split_bf16(*(const float*)(q2), *(const float*)(q2 + 4), ah[2], al[2]);
                        split_bf16(*(const float*)(q3), *(const float*)(q3 + 4), ah[3], al[3]);
#pragma unroll
                        for (int jj = 0; jj < 4; jj++) {
                            const int j = jh * 4 + jj;
                            mma16(acc[i][j], ah, bh[jj]);
                            mma16(acc[i][j], al, bh[jj]);
                            mma16(acc[i][j], ah, bl[jj]);
                        }
                    }
                }
            }

            if (c + 1 < KT_CHUNKS) {
                char* sn = (char*)smem + (((c + 1) & 1) ? TEN1 : TEN0);
                const int k0 = (c + 1) * KCH;
#pragma unroll
                for (int i = 0; i < 4; i++) {
                    const int row = (tid >> 3) + 16 * i;
                    float* pA = (float*)(sn + k8p * K8S + row * PITCH + kkb * 4);
                    pA[0] = xa[i].x; pA[1] = xa[i].y; pA[2] = xa[i].z; pA[3] = xa[i].w;
                    float* pB = (float*)(sn + TEN_BOFF + k8p * K8S + row * PITCH + kkb * 4);
                    pB[0] = wa[i].x; pB[1] = wa[i].y; pB[2] = wa[i].z; pB[3] = wa[i].w;
                }
#pragma unroll
                for (int i = 4; i < 8; i++) {
                    const int row = (tid >> 3) + 16 * i;
                    float4 va = *(const float4*)(X + (size_t)(m0 + row) * HIDDEN + k0 + c4 * 4);
                    float4 vb = *(const float4*)(W + (size_t)row * HIDDEN + k0 + c4 * 4);
                    float* pA = (float*)(sn + k8p * K8S + row * PITCH + kkb * 4);
                    pA[0] = va.x; pA[1] = va.y; pA[2] = va.z; pA[3] = va.w;
                    float* pB = (float*)(sn + TEN_BOFF + k8p * K8S + row * PITCH + kkb * 4);
                    pB[0] = vb.x; pB[1] = vb.y; pB[2] = vb.z; pB[3] = vb.w;
                }
            }
        }

        // all tensor warps done reading stages -> safe to overwrite with L
        BAR(1);
#pragma unroll
        for (int i = 0; i < 4; i++) {
            const int r0 = wm * 64 + i * 16 + g;
#pragma unroll
            for (int j = 0; j < 8; j++) {
                const int c0 = wn * 64 + j * 8 + t * 2;
                *(float2*)&L[r0 * LPITCH + c0]       = make_float2(acc[i][j][0], acc[i][j][1]);
                *(float2*)&L[(r0 + 8) * LPITCH + c0] = make_float2(acc[i][j][2], acc[i][j][3]);
            }
        }
    } else {
        // ================= FMA PATH (warps 4-7, tidf 0..127) ================
        const int tidf = tid - 128;
        const int w4 = wid - 4;
        const int fm = (w4 >> 1) & 1;
        const int fn = w4 & 1;
        const int lt = lane >> 3;          // token group (0..3)
        const int le = lane & 7;           // expert group (0..7)
        const int c4 = tidf & 7;

        unsigned long long acc2[16][4];
#pragma unroll
        for (int i = 0; i < 16; i++)
#pragma unroll
            for (int j = 0; j < 4; j++) acc2[i][j] = 0ull;

        // prologue: produce chunk 0 (k0 = K_T) into FMA0
#pragma unroll
        for (int i = 0; i < 8; i++) {
            const int row = (tidf >> 3) + 16 * i;
            float4 va = *(const float4*)(X + (size_t)(m0 + row) * HIDDEN + K_T + c4 * 4);
            float4 vb = *(const float4*)(W + (size_t)row * HIDDEN + K_T + c4 * 4);
            const float av[4] = {va.x, va.y, va.z, va.w};
            const float bv[4] = {vb.x, vb.y, vb.z, vb.w};
#pragma unroll
            for (int j = 0; j < 4; j++) {
                *(float*)(smem + FMA0 + FMA_A + (c4 * 4 + j) * FPITCH + row * 4) = av[j];
                *(float*)(smem + FMA0 + FMA_B + (c4 * 4 + j) * FPITCH + row * 4) = bv[j];
            }
        }

        const int tokb = fm * 64 + lt * 16;
        const int expb = fn * 64 + le * 8;

        float4 xa[4], wa[4];
        for (int c = 0; c < KF_CHUNKS; c++) {
            BAR(2);
            const char* sp = smem + ((c & 1) ? FMA1 : FMA0);

            if (c + 1 < KF_CHUNKS) {
                const int k0 = K_T + (c + 1) * KCH;
#pragma unroll
                for (int i = 0; i < 4; i++) {
                    const int row = (tidf >> 3) + 16 * i;
                    xa[i] = *(const float4*)(X + (size_t)(m0 + row) * HIDDEN + k0 + c4 * 4);
                    wa[i] = *(const float4*)(W + (size_t)row * HIDDEN + k0 + c4 * 4);
                }
            }

#pragma unroll 4
            for (int kr = 0; kr < KCH; kr++) {
                const char* ab = sp + FMA_A + kr * FPITCH + tokb * 4;
                float4 f0 = *(const float4*)(ab);
                float4 f1 = *(const float4*)(ab + 16);
                float4 f2 = *(const float4*)(ab + 32);
                float4 f3 = *(const float4*)(ab + 48);
                unsigned long long ad[16];
                ad[0]  = dup2(f0.x); ad[1]  = dup2(f0.y); ad[2]  = dup2(f0.z); ad[3]  = dup2(f0.w);
                ad[4]  = dup2(f1.x); ad[5]  = dup2(f1.y); ad[6]  = dup2(f1.z); ad[7]  = dup2(f1.w);
                ad[8]  = dup2(f2.x); ad[9]  = dup2(f2.y); ad[10] = dup2(f2.z); ad[11] = dup2(f2.w);
                ad[12] = dup2(f3.x); ad[13] = dup2(f3.y); ad[14] = dup2(f3.z); ad[15] = dup2(f3.w);

                const char* bb = sp + FMA_B + kr * FPITCH + expb * 4;
                unsigned long long b[4];
                b[0] = *(const unsigned long long*)(bb);
                b[1] = *(const unsigned long long*)(bb + 8);
                b[2] = *(const unsigned long long*)(bb + 16);
                b[3] = *(const unsigned long long*)(bb + 24);
#pragma unroll
                for (int i = 0; i < 16; i++)
#pragma unroll
                    for (int j = 0; j < 4; j++)
                        ffma2(acc2[i][j], ad[i], b[j]);
            }

            if (c + 1 < KF_CHUNKS) {
                char* sn = (char*)smem + (((c + 1) & 1) ? FMA1 : FMA0);
                const int k0 = K_T + (c + 1) * KCH;
#pragma unroll
                for (int i = 0; i < 4; i++) {
                    const int row = (tidf >> 3) + 16 * i;
                    const float av[4] = {xa[i].x, xa[i].y, xa[i].z, xa[i].w};
                    const float bv[4] = {wa[i].x, wa[i].y, wa[i].z, wa[i].w};
#pragma unroll
                    for (int j = 0; j < 4; j++) {
                        *(float*)(sn + FMA_A + (c4 * 4 + j) * FPITCH + row * 4) = av[j];
                        *(float*)(sn + FMA_B + (c4 * 4 + j) * FPITCH + row * 4) = bv[j];
                    }
                }
#pragma unroll
                for (int i = 4; i < 8; i++) {
                    const int row = (tidf >> 3) + 16 * i;
                    float4 va = *(const float4*)(X + (size_t)(m0 + row) * HIDDEN + k0 + c4 * 4);
                    float4 vb = *(const float4*)(W + (size_t)row * HIDDEN + k0 + c4 * 4);
                    const float av[4] = {va.x, va.y, va.z, va.w};
                    const float bv[4] = {vb.x, vb.y, vb.z, vb.w};
#pragma unroll
                    for (int j = 0; j < 4; j++) {
                        *(float*)(sn + FMA_A + (c4 * 4 + j) * FPITCH + row * 4) = av[j];
                        *(float*)(sn + FMA_B + (c4 * 4 + j) * FPITCH + row * 4) = bv[j];
                    }
                }
            }
        }

        // all fma warps done reading stages -> safe to overwrite with L2
        BAR(2);
#pragma unroll
        for (int i = 0; i < 16; i++) {
            const int tok = fm * 64 + lt * 16 + i;
#pragma unroll
            for (int j = 0; j < 4; j++) {
                const int e = fn * 64 + le * 8 + j * 2;
                float2 v = *(float2*)&acc2[i][j];
                *(float2*)&L2[tok * LPITCH + e] = v;
            }
        }
    }

    __syncthreads();

    // ---- top-9 (scores = L + L2) with risk detection ----
    float bv[4];
#pragma unroll
    for (int q = 0; q < 4; q++) bv[q] = bias[q * 32 + lane];

    for (int rr = 0; rr < 16; rr++) {
        const int row = wid * 16 + rr;
        const float* Lr  = L  + row * LPITCH;
        const float* Lr2 = L2 + row * LPITCH;

        float sv[4], wv[4];
#pragma unroll
        for (int q = 0; q < 4; q++) {
            float logit = Lr[q * 32 + lane] + Lr2[q * 32 + lane];
            float sc = 1.f / (1.f + expf(-logit));
            wv[q] = sc;
            sv[q] = sc + bv[q];
        }

        float wsel[TOPK];
        int   isel[TOPK];
        float wsum = 0.f;
        float prev = 0.f, mingap = INFINITY;

#pragma unroll
        for (int k = 0; k < TOPK + 1; k++) {
            float bs = -INFINITY; int bi = 0x7fffffff; float bw = 0.f;
#pragma unroll
            for (int q = 0; q < 4; q++) {
                int e = q * 32 + lane;
                if (sv[q] > bs || (sv[q] == bs && e < bi)) { bs = sv[q]; bi = e; bw = wv[q]; }
            }
#pragma unroll
            for (int off = 16; off; off >>= 1) {
                float os = __shfl_xor_sync(0xffffffffu, bs, off);
                int   oi = __shfl_xor_sync(0xffffffffu, bi, off);
                float ow = __shfl_xor_sync(0xffffffffu, bw, off);
                if (os > bs || (os == bs && oi < bi)) { bs = os; bi = oi; bw = ow; }
            }
            if (k > 0) mingap = fminf(mingap, prev - bs);
            prev = bs;
            if (k < TOPK) {
                isel[k] = bi; wsel[k] = bw; wsum += bw;
#pragma unroll
                for (int q = 0; q < 4; q++)
                    if (q * 32 + lane == bi) sv[q] = -INFINITY;
            }
        }

        if (lane == 0) {
            const int token = m0 + row;
            float inv = 1.f / (wsum + 1e-20f);   // ROUTED_SCALING = 1.0
#pragma unroll
            for (int k = 0; k < TOPK; k++) {
                out[(size_t)token * TOPK + k]                    = (float)isel[k];
                out[(size_t)T * TOPK + (size_t)token * TOPK + k] = wsel[k] * inv;
            }
            if (!(mingap >= DELTA)) {
                int idx = atomicAdd(&g_ctr, 1);
                g_list[idx] = token;
            }
        }
    }
}

// ---------------------------------------------------------------------------
// Exact fp32 refine of risky tokens (proven, unchanged).
// ---------------------------------------------------------------------------
__global__ void __launch_bounds__(256) refine_kernel(
    const float* __restrict__ X, const float* __restrict__ W,
    const float* __restrict__ bias, float* __restrict__ out, int T)
{
    __shared__ float Xs[RB][512];
    __shared__ float S[RB][NEXP];
    __shared__ int   tks[RB];

    const int tid  = threadIdx.x;
    const int e    = tid & 127;
    const int tg   = tid >> 7;
    const int wid  = tid >> 5;
    const int lane = tid & 31;
    const int R    = g_ctr;

    for (int b = blockIdx.x; b * RB < R; b += gridDim.x) {
        if (tid < RB) {
            int i = b * RB + tid;
            tks[tid] = (i < R) ? g_list[i] : -1;
        }
        __syncthreads();

        float acc[4] = {0.f, 0.f, 0.f, 0.f};
        const float* wrow = W + (size_t)e * HIDDEN;

        for (int c = 0; c < 8; c++) {
            const int k0 = c * 512;
#pragma unroll
            for (int i = 0; i < 4; i++) {
                int s   = tid + 256 * i;
                int tok = s >> 7;
                int f4  = s & 127;
                int tt  = tks[tok] < 0 ? 0 : tks[tok];
                *(float4*)&Xs[tok][f4 * 4] =
                    *(const float4*)(X + (size_t)tt * HIDDEN + k0 + f4 * 4);
            }
            __syncthreads();
#pragma unroll 4
            for (int f4 = 0; f4 < 128; f4++) {
                float4 w4 = *(const float4*)(wrow + k0 + f4 * 4);
#pragma unroll
                for (int j = 0; j < 4; j++) {
                    const float* xr = &Xs[tg * 4 + j][f4 * 4];
                    acc[j] = fmaf(w4.x, xr[0],
                             fmaf(w4.y, xr[1],
                             fmaf(w4.z, xr[2],
                             fmaf(w4.w, xr[3], acc[j]))));
                }
            }
            __syncthreads();
        }
#pragma unroll
        for (int j = 0; j < 4; j++) S[tg * 4 + j][e] = acc[j];
        __syncthreads();

        if (wid < RB && tks[wid] >= 0) {
            const int token = tks[wid];
            float sv[4], wv[4];
#pragma unroll
            for (int q = 0; q < 4; q++) {
                int ee = q * 32 + lane;
                float sc = 1.f / (1.f + expf(-S[wid][ee]));
                wv[q] = sc;
                sv[q] = sc + bias[ee];
            }
            float wsel[TOPK]; int isel[TOPK]; float wsum = 0.f;
#pragma unroll
            for (int k = 0; k < TOPK; k++) {
                float bs = -INFINITY; int bi = 0x7fffffff; float bw = 0.f;
#pragma unroll
                for (int q = 0; q < 4; q++) {
                    int ee = q * 32 + lane;
                    if (sv[q] > bs || (sv[q] == bs && ee < bi)) { bs = sv[q]; bi = ee; bw = wv[q]; }
                }
#pragma unroll
                for (int off = 16; off; off >>= 1) {
                    float os = __shfl_xor_sync(0xffffffffu, bs, off);
                    int   oi = __shfl_xor_sync(0xffffffffu, bi, off);
                    float ow = __shfl_xor_sync(0xffffffffu, bw, off);
                    if (os > bs || (os == bs && oi < bi)) { bs = os; bi = oi; bw = ow; }
                }
                isel[k] = bi; wsel[k] = bw; wsum += bw;
#pragma unroll
                for (int q = 0; q < 4; q++)
                    if (q * 32 + lane == bi) sv[q] = -INFINITY;
            }
            if (lane == 0) {
                float inv = 1.f / (wsum + 1e-20f);
#pragma unroll
                for (int k = 0; k < TOPK; k++) {
                    out[(size_t)token * TOPK + k]                    = (float)isel[k];
                    out[(size_t)T * TOPK + (size_t)token * TOPK + k] = wsel[k] * inv;
                }
            }
        }
        __syncthreads();
    }
}

// ---------------------------------------------------------------------------
extern "C" void kernel_launch(void* const* d_in, const int* in_sizes, int n_in,
                              void* d_out, int out_size)
{
    const float* X    = (const float*)d_in[0];
    const float* W    = (const float*)d_in[1];
    const float* bias = (const float*)d_in[2];
    float* out = (float*)d_out;

    const int T = in_sizes[0] / HIDDEN;          // 16384

    cudaFuncSetAttribute(router_fused,
                         cudaFuncAttributeMaxDynamicSharedMemorySize, SMEM_BYTES);

    zero_ctr_kernel<<<1, 1>>>();
    router_fused<<<T / TM, 256, SMEM_BYTES>>>(X, W, bias, out, T);
    refine_kernel<<<256, 256>>>(X, W, bias, out, T);
}